// round 13
// baseline (speedup 1.0000x reference)
#include <cuda_runtime.h>

// CoincidenceLIFBank: B=32 x T=4096 x D=256.
// Output: [0,B*D) pooled | [B*D,+B*D*T) spikes | +D rw | +D tw | +D beta
//
// NUMERICS FROZEN (rel_err 9.894e-4 across R6-R12):
//   rw/tw = max(x,0) + logf(1 + expf(-|x|));  sigmoid = 1/(1+expf(-x))
//   beta  = fadd(0.7, fmul(0.295, sigmoid))         (uncontracted)
//   cur   = fadd(fmul(rw, rv), fmul(tw, tv))        (UNcontracted)
//   mp    = fma(beta, m, cur); ms = fadd(mp,-1); p = (mp>=1)
//   m = p ? ms : mp;  s = p ? 1 : 0
// OOB ref reads exact 0.0f from the zero-padded smem row.
//
// R13: register-pressure surgery. Prologue/dump unrolls capped so the HOT
// LOOP sets the register budget (R12 allocated 254 for the fully-unrolled
// staging loop and then couldn't schedule the hot loop). cur[] hoisted into
// the fetch phase (identical ops/values, smaller ping-pong state). Count on
// the ALU pipe as an integer.

#define NB 32
#define NT 4096
#define ND 256
#define THRESH 1.0f
#define TILE 128
#define TSTRIDE 132          // tile row stride in floats (528B, 16B-aligned)
#define SREF_N (NT + 256)    // zero pad: delay<128 + prefetch slack

__device__ __forceinline__ float softplus_xla(float x) {
    const float u = expf(-fabsf(x));
    return __fadd_rn(fmaxf(x, 0.0f), logf(__fadd_rn(1.0f, u)));
}
__device__ __forceinline__ float sigmoid_xla(float x) {
    return 1.0f / (__fadd_rn(1.0f, expf(-x)));
}

// fetch + precompute cur for a 4-step group (independent of membrane state)
__device__ __forceinline__ void fetch_cur4(const float* __restrict__ sref,
                                           const float* __restrict__ stgt,
                                           const int delay, const int t,
                                           const float rw, const float tw,
                                           float* __restrict__ cur)
{
    const float4 v = *(const float4*)(stgt + (t & (NT - 1)));
    const float tv[4] = {v.x, v.y, v.z, v.w};
#pragma unroll
    for (int j = 0; j < 4; j++) {
        const float rv = sref[delay + t + j];
        cur[j] = __fadd_rn(__fmul_rn(rw, rv), __fmul_rn(tw, tv[j]));
    }
}

// 4 serial LIF steps from precomputed currents (frozen arithmetic)
__device__ __forceinline__ void lif4(const float beta,
                                     const float* __restrict__ cur,
                                     float& m, int& cnt,
                                     float* __restrict__ sp)
{
#pragma unroll
    for (int j = 0; j < 4; j++) {
        const float mp = __fmaf_rn(beta, m, cur[j]);
        const float ms = __fadd_rn(mp, -THRESH);
        const bool  p  = (mp >= THRESH);
        m = p ? ms : mp;
        sp[j] = p ? 1.0f : 0.0f;
        cnt += p ? 1 : 0;            // integer, ALU pipe, off the FP chain
    }
}

__global__ void __launch_bounds__(32)
lif_bank_kernel(const float* __restrict__ ref,
                const float* __restrict__ tgt,
                const int*   __restrict__ delays,
                const float* __restrict__ rw_raw,
                const float* __restrict__ tw_raw,
                const float* __restrict__ beta_raw,
                float* __restrict__ out)
{
    // 256 single-warp blocks: block -> (b, 32-d group). 8 blocks per b.
    const int lane = threadIdx.x;
    const int b    = blockIdx.x >> 3;
    const int d0   = (blockIdx.x & 7) * 32;
    const int d    = d0 + lane;

    __shared__ float sref[SREF_N];             // ref[b,:] + zero pad
    __shared__ float stgt[NT];                 // tgt[b,:]
    __shared__ float stile[32][TSTRIDE];       // spike transpose tile

    // ---- stage ref + tgt (coalesced; unroll CAPPED to keep regs low) ----
    {
        const float4* __restrict__ ref4 = (const float4*)(ref + b * NT);
        const float4* __restrict__ tgt4 = (const float4*)(tgt + b * NT);
        float4* sr4 = (float4*)sref;
        float4* st4 = (float4*)stgt;
#pragma unroll 4
        for (int i = 0; i < NT / 128; i++) {
            sr4[lane + 32 * i] = __ldg(ref4 + lane + 32 * i);
            st4[lane + 32 * i] = __ldg(tgt4 + lane + 32 * i);
        }
#pragma unroll
        for (int i = NT / 128; i < SREF_N / 128; i++)
            sr4[lane + 32 * i] = make_float4(0.f, 0.f, 0.f, 0.f);
    }

    // ---- per-bank params (frozen recipe) ----
    const float rw   = softplus_xla(rw_raw[d]);
    const float tw   = softplus_xla(tw_raw[d]);
    const float beta = __fadd_rn(0.7f, __fmul_rn(0.295f, sigmoid_xla(beta_raw[d])));
    const int   delay = delays[d];

    float* out_pooled = out;
    float* out_spk    = out + NB * ND;
    float* out_rw     = out + NB * ND + (size_t)NB * ND * NT;
    float* out_tw     = out_rw + ND;
    float* out_beta   = out_tw + ND;

    float m = 0.0f;
    int   cnt = 0;

    __syncwarp();   // staged rows visible warp-wide

    // ---- ping-pong pipeline over precomputed currents (smem-only) ----
    float curA[4], curB[4], sp[4];
    fetch_cur4(sref, stgt, delay, 0, rw, tw, curA);

    for (int tile0 = 0; tile0 < NT; tile0 += TILE) {
#pragma unroll 2
        for (int t0 = tile0; t0 < tile0 + TILE; t0 += 8) {
            fetch_cur4(sref, stgt, delay, t0 + 4, rw, tw, curB);
            lif4(beta, curA, m, cnt, sp);
            *(float4*)&stile[lane][t0 - tile0] =
                make_float4(sp[0], sp[1], sp[2], sp[3]);

            fetch_cur4(sref, stgt, delay, t0 + 8, rw, tw, curA);
            lif4(beta, curB, m, cnt, sp);
            *(float4*)&stile[lane][t0 + 4 - tile0] =
                make_float4(sp[0], sp[1], sp[2], sp[3]);
        }
        __syncwarp();

        // ---- dump: 32 rows x 512B contiguous STG.128 bursts ----
#pragma unroll 2
        for (int r = 0; r < 32; r++) {
            const float4 w = *(const float4*)&stile[r][lane * 4];
            float* dst = out_spk + (size_t)(b * ND + d0 + r) * NT + tile0;
            *(float4*)(dst + lane * 4) = w;
        }
        __syncwarp();
    }

    out_pooled[b * ND + d] = (float)cnt * (1.0f / NT);

    if (b == 0) {   // blocks 0..7 cover d = 0..255 exactly once
        out_rw[d]   = rw;
        out_tw[d]   = tw;
        out_beta[d] = beta;
    }
}

extern "C" void kernel_launch(void* const* d_in, const int* in_sizes, int n_in,
                              void* d_out, int out_size)
{
    const float* ref      = (const float*)d_in[0];
    const float* tgt      = (const float*)d_in[1];
    const int*   delays   = (const int*)  d_in[2];
    const float* rw_raw   = (const float*)d_in[3];
    const float* tw_raw   = (const float*)d_in[4];
    const float* beta_raw = (const float*)d_in[5];
    float* out = (float*)d_out;

    // 256 single-warp blocks; scan loop touches only smem.
    lif_bank_kernel<<<NB * 8, 32>>>(ref, tgt, delays, rw_raw, tw_raw,
                                    beta_raw, out);
}